// round 6
// baseline (speedup 1.0000x reference)
#include <cuda_runtime.h>
#include <math.h>

#define NN   100000
#define EE   3200000
#define DIN  256
#define DHID 256
#define DOUT 64

// ---------------- scratch (__device__ globals; no allocation allowed) -------
__device__ int   g_deg[NN];
__device__ int   g_off[NN + 1];
__device__ int   g_cur[NN];
__device__ float g_dinv[NN];
__device__ int   g_csr[EE];
__device__ __align__(16) float g_h1[(size_t)NN * DHID];
__device__ __align__(16) float g_a1[(size_t)NN * DHID];
__device__ __align__(16) float g_h2[(size_t)NN * DOUT];

// ---------------- degree / CSR build (grid-stride everywhere) ---------------
extern "C" __global__ __launch_bounds__(256) void k_count(const int* dst, int e) {
    for (int i = blockIdx.x * blockDim.x + threadIdx.x; i < e;
         i += gridDim.x * blockDim.x)
        atomicAdd(&g_deg[dst[i]], 1);
}

extern "C" __global__ __launch_bounds__(1024) void k_scan() {
    __shared__ int partial[1024];
    int t = threadIdx.x;
    const int CH = (NN + 1023) / 1024;
    int start = t * CH;
    int end   = start + CH; if (end > NN) end = NN;
    int s = 0;
    for (int i = start; i < end; i++) s += g_deg[i];
    partial[t] = s;
    __syncthreads();
    for (int d = 1; d < 1024; d <<= 1) {
        int v = (t >= d) ? partial[t - d] : 0;
        __syncthreads();
        partial[t] += v;
        __syncthreads();
    }
    int run = (t > 0) ? partial[t - 1] : 0;
    for (int i = start; i < end; i++) {
        g_off[i] = run;
        g_cur[i] = run;
        run += g_deg[i];
    }
    if (t == 1023) g_off[NN] = partial[1023];
}

extern "C" __global__ __launch_bounds__(256) void k_fill(const int* src,
                                                         const int* dst, int e) {
    for (int i = blockIdx.x * blockDim.x + threadIdx.x; i < e;
         i += gridDim.x * blockDim.x) {
        int p = atomicAdd(&g_cur[dst[i]], 1);
        g_csr[p] = src[i];
    }
}

extern "C" __global__ __launch_bounds__(256) void k_dinv() {
    for (int i = blockIdx.x * blockDim.x + threadIdx.x; i < NN;
         i += gridDim.x * blockDim.x)
        g_dinv[i] = rsqrtf((float)(g_deg[i] + 1));   // +1 self-loop
}

// ---------------- GEMM 1: g_h1 = x @ W1  (M=NN, N=256, K=256) ----------------
// 1-D grid: 2 * ceil(NN/128) blocks. BM=128, BN=128, BK=8, 256 thr, 8x8 tile.
extern "C" __global__ __launch_bounds__(256) void k_gemm1(
    const float* __restrict__ A, const float* __restrict__ B) {
    __shared__ __align__(16) float As[8][128];
    __shared__ __align__(16) float Bs[8][128];
    const int tid = threadIdx.x;
    const int bx  = blockIdx.x & 1;          // N block (0/1)
    const int by  = blockIdx.x >> 1;         // M block
    const int m0  = by * 128;
    const int n0  = bx * 128;
    const int tx  = tid & 15;                // 0..15
    const int ty  = tid >> 4;                // 0..15
    const int a_row = tid >> 1;
    const int a_kq  = (tid & 1) * 4;
    const int b_row = tid >> 5;              // 0..7
    const int b_col = (tid & 31) * 4;        // 0..124

    float acc[8][8];
#pragma unroll
    for (int i = 0; i < 8; i++)
#pragma unroll
        for (int j = 0; j < 8; j++) acc[i][j] = 0.f;

    for (int k0 = 0; k0 < DIN; k0 += 8) {
        int gm = m0 + a_row;
        float4 va = make_float4(0.f, 0.f, 0.f, 0.f);
        if (gm < NN) va = *(const float4*)(A + (size_t)gm * DIN + k0 + a_kq);
        As[a_kq + 0][a_row] = va.x;
        As[a_kq + 1][a_row] = va.y;
        As[a_kq + 2][a_row] = va.z;
        As[a_kq + 3][a_row] = va.w;
        float4 vb = *(const float4*)(B + (size_t)(k0 + b_row) * DHID + n0 + b_col);
        *(float4*)&Bs[b_row][b_col] = vb;
        __syncthreads();
#pragma unroll
        for (int kk = 0; kk < 8; kk++) {
            float a[8], b[8];
#pragma unroll
            for (int i = 0; i < 8; i++) a[i] = As[kk][ty * 8 + i];
#pragma unroll
            for (int j = 0; j < 8; j++) b[j] = Bs[kk][tx * 8 + j];
#pragma unroll
            for (int i = 0; i < 8; i++)
#pragma unroll
                for (int j = 0; j < 8; j++) acc[i][j] = fmaf(a[i], b[j], acc[i][j]);
        }
        __syncthreads();
    }
#pragma unroll
    for (int i = 0; i < 8; i++) {
        int row = m0 + ty * 8 + i;
        if (row < NN) {
            float* cp = g_h1 + (size_t)row * DHID + n0 + tx * 8;
#pragma unroll
            for (int j = 0; j < 8; j += 4)
                *(float4*)(cp + j) = make_float4(acc[i][j], acc[i][j + 1],
                                                 acc[i][j + 2], acc[i][j + 3]);
        }
    }
}

// ---------------- GEMM 2: g_h2 = g_a1 @ W2 (M=NN, N=64, K=256) ---------------
// 1-D grid: ceil(NN/128) blocks. BM=128, BN=64, BK=8, 256 thr, 8x4 tile.
extern "C" __global__ __launch_bounds__(256) void k_gemm2(
    const float* __restrict__ B) {
    __shared__ __align__(16) float As[8][128];
    __shared__ __align__(16) float Bs[8][64];
    const int tid = threadIdx.x;
    const int m0  = blockIdx.x * 128;
    const int tx  = tid & 15;                // 0..15 (cols of 4)
    const int ty  = tid >> 4;                // 0..15 (rows of 8)
    const int a_row = tid >> 1;
    const int a_kq  = (tid & 1) * 4;
    const int b_row = tid >> 4;              // 0..15 (only <8 used)
    const int b_col = (tid & 15) * 4;        // 0..60

    float acc[8][4];
#pragma unroll
    for (int i = 0; i < 8; i++)
#pragma unroll
        for (int j = 0; j < 4; j++) acc[i][j] = 0.f;

    for (int k0 = 0; k0 < DHID; k0 += 8) {
        int gm = m0 + a_row;
        float4 va = make_float4(0.f, 0.f, 0.f, 0.f);
        if (gm < NN) va = *(const float4*)(g_a1 + (size_t)gm * DHID + k0 + a_kq);
        As[a_kq + 0][a_row] = va.x;
        As[a_kq + 1][a_row] = va.y;
        As[a_kq + 2][a_row] = va.z;
        As[a_kq + 3][a_row] = va.w;
        if (b_row < 8) {
            float4 vb = *(const float4*)(B + (size_t)(k0 + b_row) * DOUT + b_col);
            *(float4*)&Bs[b_row][b_col] = vb;
        }
        __syncthreads();
#pragma unroll
        for (int kk = 0; kk < 8; kk++) {
            float a[8], b[4];
#pragma unroll
            for (int i = 0; i < 8; i++) a[i] = As[kk][ty * 8 + i];
#pragma unroll
            for (int j = 0; j < 4; j++) b[j] = Bs[kk][tx * 4 + j];
#pragma unroll
            for (int i = 0; i < 8; i++)
#pragma unroll
                for (int j = 0; j < 4; j++) acc[i][j] = fmaf(a[i], b[j], acc[i][j]);
        }
        __syncthreads();
    }
#pragma unroll
    for (int i = 0; i < 8; i++) {
        int row = m0 + ty * 8 + i;
        if (row < NN)
            *(float4*)(g_h2 + (size_t)row * DOUT + tx * 4) =
                make_float4(acc[i][0], acc[i][1], acc[i][2], acc[i][3]);
    }
}

// ---------------- layer-1 aggregation: one warp per dst node -----------------
extern "C" __global__ __launch_bounds__(256) void k_agg1(const float* __restrict__ b1) {
    int lane = threadIdx.x & 31;
    int warps = (gridDim.x * blockDim.x) >> 5;
    for (int w = (blockIdx.x * blockDim.x + threadIdx.x) >> 5; w < NN; w += warps) {
        float di = g_dinv[w];
        const float4* self = (const float4*)(g_h1 + (size_t)w * DHID);
        float4 acc0 = self[lane];
        float4 acc1 = self[lane + 32];
        acc0.x *= di; acc0.y *= di; acc0.z *= di; acc0.w *= di;
        acc1.x *= di; acc1.y *= di; acc1.z *= di; acc1.w *= di;
        int e   = g_off[w];
        int end = g_off[w + 1];
        for (; e < end; e++) {
            int   s  = g_csr[e];
            float ws = g_dinv[s];
            const float4* r = (const float4*)(g_h1 + (size_t)s * DHID);
            float4 v0 = r[lane], v1 = r[lane + 32];
            acc0.x += ws * v0.x; acc0.y += ws * v0.y;
            acc0.z += ws * v0.z; acc0.w += ws * v0.w;
            acc1.x += ws * v1.x; acc1.y += ws * v1.y;
            acc1.z += ws * v1.z; acc1.w += ws * v1.w;
        }
        float4 bb0 = ((const float4*)b1)[lane];
        float4 bb1 = ((const float4*)b1)[lane + 32];
        float4 o0, o1;
        o0.x = fmaxf(di * acc0.x + bb0.x, 0.f);
        o0.y = fmaxf(di * acc0.y + bb0.y, 0.f);
        o0.z = fmaxf(di * acc0.z + bb0.z, 0.f);
        o0.w = fmaxf(di * acc0.w + bb0.w, 0.f);
        o1.x = fmaxf(di * acc1.x + bb1.x, 0.f);
        o1.y = fmaxf(di * acc1.y + bb1.y, 0.f);
        o1.z = fmaxf(di * acc1.z + bb1.z, 0.f);
        o1.w = fmaxf(di * acc1.w + bb1.w, 0.f);
        float4* op = (float4*)(g_a1 + (size_t)w * DHID);
        op[lane]      = o0;
        op[lane + 32] = o1;
    }
}

// ---------------- layer-2 aggregation + bias + log_softmax -------------------
extern "C" __global__ __launch_bounds__(256) void k_agg2(const float* __restrict__ b2,
                                                         float* __restrict__ out) {
    int lane = threadIdx.x & 31;
    int warps = (gridDim.x * blockDim.x) >> 5;
    for (int w = (blockIdx.x * blockDim.x + threadIdx.x) >> 5; w < NN; w += warps) {
        float di = g_dinv[w];
        const float2* self = (const float2*)(g_h2 + (size_t)w * DOUT);
        float2 acc = self[lane];
        acc.x *= di; acc.y *= di;
        int e   = g_off[w];
        int end = g_off[w + 1];
        for (; e < end; e++) {
            int   s  = g_csr[e];
            float ws = g_dinv[s];
            float2 v = ((const float2*)(g_h2 + (size_t)s * DOUT))[lane];
            acc.x += ws * v.x;
            acc.y += ws * v.y;
        }
        float2 bb = ((const float2*)b2)[lane];
        float zx = di * acc.x + bb.x;
        float zy = di * acc.y + bb.y;
        float m = fmaxf(zx, zy);
#pragma unroll
        for (int o = 16; o; o >>= 1) m = fmaxf(m, __shfl_xor_sync(0xffffffffu, m, o));
        float s = expf(zx - m) + expf(zy - m);
#pragma unroll
        for (int o = 16; o; o >>= 1) s += __shfl_xor_sync(0xffffffffu, s, o);
        float lse = m + logf(s);
        float2 r; r.x = zx - lse; r.y = zy - lse;
        ((float2*)(out + (size_t)w * DOUT))[lane] = r;
    }
}

// ---------------- launch ------------------------------------------------------
extern "C" void kernel_launch(void* const* d_in, const int* in_sizes, int n_in,
                              void* d_out, int out_size) {
    // Identify inputs by element count — all six counts are distinct.
    const float* x  = nullptr;
    const int*   ei = nullptr;
    const float* W1 = nullptr;
    const float* b1 = nullptr;
    const float* W2 = nullptr;
    const float* b2 = nullptr;
    for (int i = 0; i < n_in; i++) {
        switch (in_sizes[i]) {
            case NN * DIN:    x  = (const float*)d_in[i]; break;  // 25600000
            case 2 * EE:      ei = (const int*)d_in[i];   break;  //  6400000
            case DIN * DHID:  W1 = (const float*)d_in[i]; break;  //    65536
            case DHID:        b1 = (const float*)d_in[i]; break;  //      256
            case DHID * DOUT: W2 = (const float*)d_in[i]; break;  //    16384
            case DOUT:        b2 = (const float*)d_in[i]; break;  //       64
            default: break;
        }
    }
    float* out = (float*)d_out;
    const int* src = ei;        // row-major (2, E): row 0 = src, row 1 = dst
    const int* dst = ei + EE;

    // Explicitly zero all scratch each call (capture-legal memset nodes).
    int*   p_deg;  cudaGetSymbolAddress((void**)&p_deg,  g_deg);
    float* p_h1;   cudaGetSymbolAddress((void**)&p_h1,   g_h1);
    float* p_a1;   cudaGetSymbolAddress((void**)&p_a1,   g_a1);
    float* p_h2;   cudaGetSymbolAddress((void**)&p_h2,   g_h2);
    cudaMemsetAsync(p_deg, 0, NN * sizeof(int));
    cudaMemsetAsync(p_h1,  0, (size_t)NN * DHID * sizeof(float));
    cudaMemsetAsync(p_a1,  0, (size_t)NN * DHID * sizeof(float));
    cudaMemsetAsync(p_h2,  0, (size_t)NN * DOUT * sizeof(float));

    // CSR build + normalization
    k_count<<<2048, 256>>>(dst, EE);
    k_scan<<<1, 1024>>>();
    k_fill<<<2048, 256>>>(src, dst, EE);
    k_dinv<<<512, 256>>>();

    // layer 1
    k_gemm1<<<2 * ((NN + 127) / 128), 256>>>(x, W1);
    k_agg1<<<12500, 256>>>(b1);

    // layer 2
    k_gemm2<<<(NN + 127) / 128, 256>>>(W2);
    k_agg2<<<12500, 256>>>(b2, out);
}

// round 7
// speedup vs baseline: 1.0461x; 1.0461x over previous
#include <cuda_runtime.h>
#include <math.h>

#define NN   100000
#define EE   3200000
#define DIN  256
#define DHID 256
#define DOUT 64

// ---------------- scratch (__device__ globals; no allocation allowed) -------
__device__ int   g_deg[NN];
__device__ int   g_off[NN + 1];
__device__ int   g_cur[NN];
__device__ float g_dinv[NN];
__device__ int   g_csr[EE];
__device__ __align__(16) float g_h1[(size_t)NN * DHID];
__device__ __align__(16) float g_a1[(size_t)NN * DHID];
__device__ __align__(16) float g_h2[(size_t)NN * DOUT];

// ---------------- f32x2 packed-FMA helpers (sm_10x) --------------------------
__device__ __forceinline__ unsigned long long packf2(float x, float y) {
    unsigned long long r;
    asm("mov.b64 %0, {%1, %2};" : "=l"(r) : "f"(x), "f"(y));
    return r;
}
__device__ __forceinline__ void fmaf2(unsigned long long& d,
                                      unsigned long long a,
                                      unsigned long long b) {
    asm("fma.rn.f32x2 %0, %1, %2, %0;" : "+l"(d) : "l"(a), "l"(b));
}
__device__ __forceinline__ void unpackf2(unsigned long long v, float& x, float& y) {
    asm("mov.b64 {%0, %1}, %2;" : "=f"(x), "=f"(y) : "l"(v));
}

// ---------------- degree / CSR build (grid-stride everywhere) ---------------
extern "C" __global__ __launch_bounds__(256) void k_count(const int* dst, int e) {
    for (int i = blockIdx.x * blockDim.x + threadIdx.x; i < e;
         i += gridDim.x * blockDim.x)
        atomicAdd(&g_deg[dst[i]], 1);
}

extern "C" __global__ __launch_bounds__(1024) void k_scan() {
    __shared__ int partial[1024];
    int t = threadIdx.x;
    const int CH = (NN + 1023) / 1024;
    int start = t * CH;
    int end   = start + CH; if (end > NN) end = NN;
    int s = 0;
    for (int i = start; i < end; i++) s += g_deg[i];
    partial[t] = s;
    __syncthreads();
    for (int d = 1; d < 1024; d <<= 1) {
        int v = (t >= d) ? partial[t - d] : 0;
        __syncthreads();
        partial[t] += v;
        __syncthreads();
    }
    int run = (t > 0) ? partial[t - 1] : 0;
    for (int i = start; i < end; i++) {
        g_off[i] = run;
        g_cur[i] = run;
        run += g_deg[i];
    }
    if (t == 1023) g_off[NN] = partial[1023];
}

extern "C" __global__ __launch_bounds__(256) void k_fill(const int* src,
                                                         const int* dst, int e) {
    for (int i = blockIdx.x * blockDim.x + threadIdx.x; i < e;
         i += gridDim.x * blockDim.x) {
        int p = atomicAdd(&g_cur[dst[i]], 1);
        g_csr[p] = src[i];
    }
}

extern "C" __global__ __launch_bounds__(256) void k_dinv() {
    for (int i = blockIdx.x * blockDim.x + threadIdx.x; i < NN;
         i += gridDim.x * blockDim.x)
        g_dinv[i] = rsqrtf((float)(g_deg[i] + 1));   // +1 self-loop
}

// ---------------- GEMM 1: g_h1 = x @ W1  (M=NN, N=256, K=256) ----------------
// BM=128, BN=128, BK=8, 256 thr, 8x8 thread tile, f32x2 packed FMA.
extern "C" __global__ __launch_bounds__(256) void k_gemm1(
    const float* __restrict__ A, const float* __restrict__ B) {
    __shared__ __align__(16) float As[8][128];
    __shared__ __align__(16) float Bs[8][128];
    const int tid = threadIdx.x;
    const int bx  = blockIdx.x & 1;          // N block (0/1)
    const int by  = blockIdx.x >> 1;         // M block
    const int m0  = by * 128;
    const int n0  = bx * 128;
    const int tx  = tid & 15;                // 0..15
    const int ty  = tid >> 4;                // 0..15
    const int a_row = tid >> 1;
    const int a_kq  = (tid & 1) * 4;
    const int b_row = tid >> 5;              // 0..7
    const int b_col = (tid & 31) * 4;        // 0..124

    unsigned long long acc[8][4];
#pragma unroll
    for (int i = 0; i < 8; i++)
#pragma unroll
        for (int j = 0; j < 4; j++) acc[i][j] = 0ull;

    for (int k0 = 0; k0 < DIN; k0 += 8) {
        int gm = m0 + a_row;
        float4 va = make_float4(0.f, 0.f, 0.f, 0.f);
        if (gm < NN) va = *(const float4*)(A + (size_t)gm * DIN + k0 + a_kq);
        As[a_kq + 0][a_row] = va.x;
        As[a_kq + 1][a_row] = va.y;
        As[a_kq + 2][a_row] = va.z;
        As[a_kq + 3][a_row] = va.w;
        float4 vb = *(const float4*)(B + (size_t)(k0 + b_row) * DHID + n0 + b_col);
        *(float4*)&Bs[b_row][b_col] = vb;
        __syncthreads();
#pragma unroll
        for (int kk = 0; kk < 8; kk++) {
            float a[8];
#pragma unroll
            for (int i = 0; i < 8; i++) a[i] = As[kk][ty * 8 + i];
            unsigned long long ad[8];
#pragma unroll
            for (int i = 0; i < 8; i++) ad[i] = packf2(a[i], a[i]);
            const unsigned long long* bp =
                (const unsigned long long*)&Bs[kk][tx * 8];
            unsigned long long bv[4];
#pragma unroll
            for (int j = 0; j < 4; j++) bv[j] = bp[j];
#pragma unroll
            for (int i = 0; i < 8; i++)
#pragma unroll
                for (int j = 0; j < 4; j++) fmaf2(acc[i][j], ad[i], bv[j]);
        }
        __syncthreads();
    }
#pragma unroll
    for (int i = 0; i < 8; i++) {
        int row = m0 + ty * 8 + i;
        if (row < NN) {
            float* cp = g_h1 + (size_t)row * DHID + n0 + tx * 8;
#pragma unroll
            for (int j = 0; j < 4; j++) {
                float lo, hi;
                unpackf2(acc[i][j], lo, hi);
                cp[2 * j]     = lo;
                cp[2 * j + 1] = hi;
            }
        }
    }
}

// ---------------- GEMM 2: g_h2 = g_a1 @ W2 (M=NN, N=64, K=256) ---------------
// BM=128, BN=64, BK=8, 256 thr, 8x4 thread tile, f32x2 packed FMA.
extern "C" __global__ __launch_bounds__(256) void k_gemm2(
    const float* __restrict__ B) {
    __shared__ __align__(16) float As[8][128];
    __shared__ __align__(16) float Bs[8][64];
    const int tid = threadIdx.x;
    const int m0  = blockIdx.x * 128;
    const int tx  = tid & 15;                // 0..15 (cols of 4)
    const int ty  = tid >> 4;                // 0..15 (rows of 8)
    const int a_row = tid >> 1;
    const int a_kq  = (tid & 1) * 4;
    const int b_row = tid >> 4;              // only <8 used
    const int b_col = (tid & 15) * 4;        // 0..60

    unsigned long long acc[8][2];
#pragma unroll
    for (int i = 0; i < 8; i++) { acc[i][0] = 0ull; acc[i][1] = 0ull; }

    for (int k0 = 0; k0 < DHID; k0 += 8) {
        int gm = m0 + a_row;
        float4 va = make_float4(0.f, 0.f, 0.f, 0.f);
        if (gm < NN) va = *(const float4*)(g_a1 + (size_t)gm * DHID + k0 + a_kq);
        As[a_kq + 0][a_row] = va.x;
        As[a_kq + 1][a_row] = va.y;
        As[a_kq + 2][a_row] = va.z;
        As[a_kq + 3][a_row] = va.w;
        if (b_row < 8) {
            float4 vb = *(const float4*)(B + (size_t)(k0 + b_row) * DOUT + b_col);
            *(float4*)&Bs[b_row][b_col] = vb;
        }
        __syncthreads();
#pragma unroll
        for (int kk = 0; kk < 8; kk++) {
            const unsigned long long* bp =
                (const unsigned long long*)&Bs[kk][tx * 4];
            unsigned long long bv0 = bp[0], bv1 = bp[1];
#pragma unroll
            for (int i = 0; i < 8; i++) {
                float av = As[kk][ty * 8 + i];
                unsigned long long ad = packf2(av, av);
                fmaf2(acc[i][0], ad, bv0);
                fmaf2(acc[i][1], ad, bv1);
            }
        }
        __syncthreads();
    }
#pragma unroll
    for (int i = 0; i < 8; i++) {
        int row = m0 + ty * 8 + i;
        if (row < NN) {
            float v0, v1, v2, v3;
            unpackf2(acc[i][0], v0, v1);
            unpackf2(acc[i][1], v2, v3);
            *(float4*)(g_h2 + (size_t)row * DOUT + tx * 4) =
                make_float4(v0, v1, v2, v3);
        }
    }
}

// ---------------- layer-1 aggregation: one warp per dst node -----------------
extern "C" __global__ __launch_bounds__(256) void k_agg1(const float* __restrict__ b1) {
    int lane = threadIdx.x & 31;
    int warps = (gridDim.x * blockDim.x) >> 5;
    for (int w = (blockIdx.x * blockDim.x + threadIdx.x) >> 5; w < NN; w += warps) {
        float di = g_dinv[w];
        const float4* self = (const float4*)(g_h1 + (size_t)w * DHID);
        float4 acc0 = self[lane];
        float4 acc1 = self[lane + 32];
        acc0.x *= di; acc0.y *= di; acc0.z *= di; acc0.w *= di;
        acc1.x *= di; acc1.y *= di; acc1.z *= di; acc1.w *= di;
        int e   = g_off[w];
        int end = g_off[w + 1];
        for (; e < end; e++) {
            int   s  = g_csr[e];
            float ws = g_dinv[s];
            const float4* r = (const float4*)(g_h1 + (size_t)s * DHID);
            float4 v0 = r[lane], v1 = r[lane + 32];
            acc0.x += ws * v0.x; acc0.y += ws * v0.y;
            acc0.z += ws * v0.z; acc0.w += ws * v0.w;
            acc1.x += ws * v1.x; acc1.y += ws * v1.y;
            acc1.z += ws * v1.z; acc1.w += ws * v1.w;
        }
        float4 bb0 = ((const float4*)b1)[lane];
        float4 bb1 = ((const float4*)b1)[lane + 32];
        float4 o0, o1;
        o0.x = fmaxf(di * acc0.x + bb0.x, 0.f);
        o0.y = fmaxf(di * acc0.y + bb0.y, 0.f);
        o0.z = fmaxf(di * acc0.z + bb0.z, 0.f);
        o0.w = fmaxf(di * acc0.w + bb0.w, 0.f);
        o1.x = fmaxf(di * acc1.x + bb1.x, 0.f);
        o1.y = fmaxf(di * acc1.y + bb1.y, 0.f);
        o1.z = fmaxf(di * acc1.z + bb1.z, 0.f);
        o1.w = fmaxf(di * acc1.w + bb1.w, 0.f);
        float4* op = (float4*)(g_a1 + (size_t)w * DHID);
        op[lane]      = o0;
        op[lane + 32] = o1;
    }
}

// ---------------- layer-2 aggregation + bias + log_softmax -------------------
extern "C" __global__ __launch_bounds__(256) void k_agg2(const float* __restrict__ b2,
                                                         float* __restrict__ out) {
    int lane = threadIdx.x & 31;
    int warps = (gridDim.x * blockDim.x) >> 5;
    for (int w = (blockIdx.x * blockDim.x + threadIdx.x) >> 5; w < NN; w += warps) {
        float di = g_dinv[w];
        const float2* self = (const float2*)(g_h2 + (size_t)w * DOUT);
        float2 acc = self[lane];
        acc.x *= di; acc.y *= di;
        int e   = g_off[w];
        int end = g_off[w + 1];
        for (; e < end; e++) {
            int   s  = g_csr[e];
            float ws = g_dinv[s];
            float2 v = ((const float2*)(g_h2 + (size_t)s * DOUT))[lane];
            acc.x += ws * v.x;
            acc.y += ws * v.y;
        }
        float2 bb = ((const float2*)b2)[lane];
        float zx = di * acc.x + bb.x;
        float zy = di * acc.y + bb.y;
        float m = fmaxf(zx, zy);
#pragma unroll
        for (int o = 16; o; o >>= 1) m = fmaxf(m, __shfl_xor_sync(0xffffffffu, m, o));
        float s = expf(zx - m) + expf(zy - m);
#pragma unroll
        for (int o = 16; o; o >>= 1) s += __shfl_xor_sync(0xffffffffu, s, o);
        float lse = m + logf(s);
        float2 r; r.x = zx - lse; r.y = zy - lse;
        ((float2*)(out + (size_t)w * DOUT))[lane] = r;
    }
}

// ---------------- launch ------------------------------------------------------
extern "C" void kernel_launch(void* const* d_in, const int* in_sizes, int n_in,
                              void* d_out, int out_size) {
    // Identify inputs by element count — all six counts are distinct.
    const float* x  = nullptr;
    const int*   ei = nullptr;
    const float* W1 = nullptr;
    const float* b1 = nullptr;
    const float* W2 = nullptr;
    const float* b2 = nullptr;
    for (int i = 0; i < n_in; i++) {
        switch (in_sizes[i]) {
            case NN * DIN:    x  = (const float*)d_in[i]; break;  // 25600000
            case 2 * EE:      ei = (const int*)d_in[i];   break;  //  6400000
            case DIN * DHID:  W1 = (const float*)d_in[i]; break;  //    65536
            case DHID:        b1 = (const float*)d_in[i]; break;  //      256
            case DHID * DOUT: W2 = (const float*)d_in[i]; break;  //    16384
            case DOUT:        b2 = (const float*)d_in[i]; break;  //       64
            default: break;
        }
    }
    float* out = (float*)d_out;
    const int* src = ei;        // row-major (2, E): row 0 = src, row 1 = dst
    const int* dst = ei + EE;

    // Only g_deg needs zeroing (h1/a1/h2 are fully overwritten before read).
    int* p_deg;  cudaGetSymbolAddress((void**)&p_deg, g_deg);
    cudaMemsetAsync(p_deg, 0, NN * sizeof(int));

    // CSR build + normalization
    k_count<<<2048, 256>>>(dst, EE);
    k_scan<<<1, 1024>>>();
    k_fill<<<2048, 256>>>(src, dst, EE);
    k_dinv<<<512, 256>>>();

    // layer 1
    k_gemm1<<<2 * ((NN + 127) / 128), 256>>>(x, W1);
    k_agg1<<<12500, 256>>>(b1);

    // layer 2
    k_gemm2<<<(NN + 127) / 128, 256>>>(W2);
    k_agg2<<<12500, 256>>>(b2, out);
}

// round 8
// speedup vs baseline: 1.1718x; 1.1202x over previous
#include <cuda_runtime.h>
#include <cuda_bf16.h>
#include <math.h>

#define NN   100000
#define EE   3200000
#define DIN  256
#define DHID 256
#define DOUT 64

// ---------------- scratch (__device__ globals; no allocation allowed) -------
__device__ int   g_deg[NN];
__device__ int   g_off[NN + 1];
__device__ int   g_cur[NN];
__device__ float g_dinv[NN];
__device__ int   g_csr[EE];
__device__ __align__(16) __nv_bfloat16 g_h1[(size_t)NN * DHID];  // bf16 x@W1
__device__ __align__(16) float         g_a1[(size_t)NN * DHID];  // fp32 relu(agg)
__device__ __align__(16) __nv_bfloat16 g_h2[(size_t)NN * DOUT];  // bf16 a1@W2

// ---------------- f32x2 packed-FMA helpers (sm_10x) --------------------------
__device__ __forceinline__ unsigned long long packf2(float x, float y) {
    unsigned long long r;
    asm("mov.b64 %0, {%1, %2};" : "=l"(r) : "f"(x), "f"(y));
    return r;
}
__device__ __forceinline__ void fmaf2(unsigned long long& d,
                                      unsigned long long a,
                                      unsigned long long b) {
    asm("fma.rn.f32x2 %0, %1, %2, %0;" : "+l"(d) : "l"(a), "l"(b));
}
__device__ __forceinline__ void unpackf2(unsigned long long v, float& x, float& y) {
    asm("mov.b64 {%0, %1}, %2;" : "=f"(x), "=f"(y) : "l"(v));
}
// bf16x2 from (lo, hi) floats: d.lo = lo, d.hi = hi
__device__ __forceinline__ unsigned int bf2(float lo, float hi) {
    unsigned int r;
    asm("cvt.rn.bf16x2.f32 %0, %1, %2;" : "=r"(r) : "f"(hi), "f"(lo));
    return r;
}

// ---------------- degree / CSR build (grid-stride everywhere) ---------------
extern "C" __global__ __launch_bounds__(256) void k_count(const int* dst, int e) {
    for (int i = blockIdx.x * blockDim.x + threadIdx.x; i < e;
         i += gridDim.x * blockDim.x)
        atomicAdd(&g_deg[dst[i]], 1);
}

extern "C" __global__ __launch_bounds__(1024) void k_scan() {
    __shared__ int partial[1024];
    int t = threadIdx.x;
    const int CH = (NN + 1023) / 1024;
    int start = t * CH;
    int end   = start + CH; if (end > NN) end = NN;
    int s = 0;
    for (int i = start; i < end; i++) s += g_deg[i];
    partial[t] = s;
    __syncthreads();
    for (int d = 1; d < 1024; d <<= 1) {
        int v = (t >= d) ? partial[t - d] : 0;
        __syncthreads();
        partial[t] += v;
        __syncthreads();
    }
    int run = (t > 0) ? partial[t - 1] : 0;
    for (int i = start; i < end; i++) {
        g_off[i] = run;
        g_cur[i] = run;
        run += g_deg[i];
    }
    if (t == 1023) g_off[NN] = partial[1023];
}

extern "C" __global__ __launch_bounds__(256) void k_fill(const int* src,
                                                         const int* dst, int e) {
    for (int i = blockIdx.x * blockDim.x + threadIdx.x; i < e;
         i += gridDim.x * blockDim.x) {
        int p = atomicAdd(&g_cur[dst[i]], 1);
        g_csr[p] = src[i];
    }
}

extern "C" __global__ __launch_bounds__(256) void k_dinv() {
    for (int i = blockIdx.x * blockDim.x + threadIdx.x; i < NN;
         i += gridDim.x * blockDim.x)
        g_dinv[i] = rsqrtf((float)(g_deg[i] + 1));   // +1 self-loop
}

// ---------------- GEMM 1: g_h1(bf16) = x @ W1 (M=NN, N=256, K=256) -----------
extern "C" __global__ __launch_bounds__(256) void k_gemm1(
    const float* __restrict__ A, const float* __restrict__ B) {
    __shared__ __align__(16) float As[8][128];
    __shared__ __align__(16) float Bs[8][128];
    const int tid = threadIdx.x;
    const int bx  = blockIdx.x & 1;
    const int by  = blockIdx.x >> 1;
    const int m0  = by * 128;
    const int n0  = bx * 128;
    const int tx  = tid & 15;
    const int ty  = tid >> 4;
    const int a_row = tid >> 1;
    const int a_kq  = (tid & 1) * 4;
    const int b_row = tid >> 5;
    const int b_col = (tid & 31) * 4;

    unsigned long long acc[8][4];
#pragma unroll
    for (int i = 0; i < 8; i++)
#pragma unroll
        for (int j = 0; j < 4; j++) acc[i][j] = 0ull;

    for (int k0 = 0; k0 < DIN; k0 += 8) {
        int gm = m0 + a_row;
        float4 va = make_float4(0.f, 0.f, 0.f, 0.f);
        if (gm < NN) va = *(const float4*)(A + (size_t)gm * DIN + k0 + a_kq);
        As[a_kq + 0][a_row] = va.x;
        As[a_kq + 1][a_row] = va.y;
        As[a_kq + 2][a_row] = va.z;
        As[a_kq + 3][a_row] = va.w;
        float4 vb = *(const float4*)(B + (size_t)(k0 + b_row) * DHID + n0 + b_col);
        *(float4*)&Bs[b_row][b_col] = vb;
        __syncthreads();
#pragma unroll
        for (int kk = 0; kk < 8; kk++) {
            unsigned long long ad[8];
#pragma unroll
            for (int i = 0; i < 8; i++) {
                float av = As[kk][ty * 8 + i];
                ad[i] = packf2(av, av);
            }
            const unsigned long long* bp =
                (const unsigned long long*)&Bs[kk][tx * 8];
            unsigned long long bv[4];
#pragma unroll
            for (int j = 0; j < 4; j++) bv[j] = bp[j];
#pragma unroll
            for (int i = 0; i < 8; i++)
#pragma unroll
                for (int j = 0; j < 4; j++) fmaf2(acc[i][j], ad[i], bv[j]);
        }
        __syncthreads();
    }
#pragma unroll
    for (int i = 0; i < 8; i++) {
        int row = m0 + ty * 8 + i;
        if (row < NN) {
            uint4 pk;
            float lo, hi;
            unpackf2(acc[i][0], lo, hi); pk.x = bf2(lo, hi);
            unpackf2(acc[i][1], lo, hi); pk.y = bf2(lo, hi);
            unpackf2(acc[i][2], lo, hi); pk.z = bf2(lo, hi);
            unpackf2(acc[i][3], lo, hi); pk.w = bf2(lo, hi);
            *(uint4*)(g_h1 + (size_t)row * DHID + n0 + tx * 8) = pk;
        }
    }
}

// ---------------- GEMM 2: g_h2(bf16) = g_a1 @ W2 (M=NN, N=64, K=256) ---------
extern "C" __global__ __launch_bounds__(256) void k_gemm2(
    const float* __restrict__ B) {
    __shared__ __align__(16) float As[8][128];
    __shared__ __align__(16) float Bs[8][64];
    const int tid = threadIdx.x;
    const int m0  = blockIdx.x * 128;
    const int tx  = tid & 15;
    const int ty  = tid >> 4;
    const int a_row = tid >> 1;
    const int a_kq  = (tid & 1) * 4;
    const int b_row = tid >> 4;
    const int b_col = (tid & 15) * 4;

    unsigned long long acc[8][2];
#pragma unroll
    for (int i = 0; i < 8; i++) { acc[i][0] = 0ull; acc[i][1] = 0ull; }

    for (int k0 = 0; k0 < DHID; k0 += 8) {
        int gm = m0 + a_row;
        float4 va = make_float4(0.f, 0.f, 0.f, 0.f);
        if (gm < NN) va = *(const float4*)(g_a1 + (size_t)gm * DHID + k0 + a_kq);
        As[a_kq + 0][a_row] = va.x;
        As[a_kq + 1][a_row] = va.y;
        As[a_kq + 2][a_row] = va.z;
        As[a_kq + 3][a_row] = va.w;
        if (b_row < 8) {
            float4 vb = *(const float4*)(B + (size_t)(k0 + b_row) * DOUT + b_col);
            *(float4*)&Bs[b_row][b_col] = vb;
        }
        __syncthreads();
#pragma unroll
        for (int kk = 0; kk < 8; kk++) {
            const unsigned long long* bp =
                (const unsigned long long*)&Bs[kk][tx * 4];
            unsigned long long bv0 = bp[0], bv1 = bp[1];
#pragma unroll
            for (int i = 0; i < 8; i++) {
                float av = As[kk][ty * 8 + i];
                unsigned long long ad = packf2(av, av);
                fmaf2(acc[i][0], ad, bv0);
                fmaf2(acc[i][1], ad, bv1);
            }
        }
        __syncthreads();
    }
#pragma unroll
    for (int i = 0; i < 8; i++) {
        int row = m0 + ty * 8 + i;
        if (row < NN) {
            uint2 pk;
            float lo, hi;
            unpackf2(acc[i][0], lo, hi); pk.x = bf2(lo, hi);
            unpackf2(acc[i][1], lo, hi); pk.y = bf2(lo, hi);
            *(uint2*)(g_h2 + (size_t)row * DOUT + tx * 4) = pk;
        }
    }
}

// ---------------- layer-1 aggregation: one warp per dst node -----------------
// lane covers 8 contiguous cols [lane*8, lane*8+8) -> one uint4 (8 bf16) load.
extern "C" __global__ __launch_bounds__(256) void k_agg1(const float* __restrict__ b1) {
    int lane = threadIdx.x & 31;
    int warps = (gridDim.x * blockDim.x) >> 5;
    for (int w = (blockIdx.x * blockDim.x + threadIdx.x) >> 5; w < NN; w += warps) {
        float di = g_dinv[w];
        float acc[8];
        {
            uint4 v = ((const uint4*)(g_h1 + (size_t)w * DHID))[lane];
            const unsigned int* u = (const unsigned int*)&v;
#pragma unroll
            for (int q = 0; q < 4; q++) {
                float2 f = __bfloat1622float2(
                    *reinterpret_cast<const __nv_bfloat162*>(&u[q]));
                acc[2 * q]     = di * f.x;
                acc[2 * q + 1] = di * f.y;
            }
        }
        int e   = g_off[w];
        int end = g_off[w + 1];
        for (; e < end; e++) {
            int   s  = g_csr[e];
            float ws = g_dinv[s];
            uint4 v = ((const uint4*)(g_h1 + (size_t)s * DHID))[lane];
            const unsigned int* u = (const unsigned int*)&v;
#pragma unroll
            for (int q = 0; q < 4; q++) {
                float2 f = __bfloat1622float2(
                    *reinterpret_cast<const __nv_bfloat162*>(&u[q]));
                acc[2 * q]     = fmaf(ws, f.x, acc[2 * q]);
                acc[2 * q + 1] = fmaf(ws, f.y, acc[2 * q + 1]);
            }
        }
        float4 bb0 = ((const float4*)b1)[lane * 2];
        float4 bb1 = ((const float4*)b1)[lane * 2 + 1];
        float4 o0, o1;
        o0.x = fmaxf(di * acc[0] + bb0.x, 0.f);
        o0.y = fmaxf(di * acc[1] + bb0.y, 0.f);
        o0.z = fmaxf(di * acc[2] + bb0.z, 0.f);
        o0.w = fmaxf(di * acc[3] + bb0.w, 0.f);
        o1.x = fmaxf(di * acc[4] + bb1.x, 0.f);
        o1.y = fmaxf(di * acc[5] + bb1.y, 0.f);
        o1.z = fmaxf(di * acc[6] + bb1.z, 0.f);
        o1.w = fmaxf(di * acc[7] + bb1.w, 0.f);
        float4* op = (float4*)(g_a1 + (size_t)w * DHID + lane * 8);
        op[0] = o0;
        op[1] = o1;
    }
}

// ---------------- layer-2 aggregation + bias + log_softmax -------------------
// lane covers cols {2*lane, 2*lane+1} -> one uint (bf16x2) load per edge.
extern "C" __global__ __launch_bounds__(256) void k_agg2(const float* __restrict__ b2,
                                                         float* __restrict__ out) {
    int lane = threadIdx.x & 31;
    int warps = (gridDim.x * blockDim.x) >> 5;
    for (int w = (blockIdx.x * blockDim.x + threadIdx.x) >> 5; w < NN; w += warps) {
        float di = g_dinv[w];
        float ax, ay;
        {
            unsigned int v = ((const unsigned int*)(g_h2 + (size_t)w * DOUT))[lane];
            float2 f = __bfloat1622float2(
                *reinterpret_cast<const __nv_bfloat162*>(&v));
            ax = di * f.x;
            ay = di * f.y;
        }
        int e   = g_off[w];
        int end = g_off[w + 1];
        for (; e < end; e++) {
            int   s  = g_csr[e];
            float ws = g_dinv[s];
            unsigned int v = ((const unsigned int*)(g_h2 + (size_t)s * DOUT))[lane];
            float2 f = __bfloat1622float2(
                *reinterpret_cast<const __nv_bfloat162*>(&v));
            ax = fmaf(ws, f.x, ax);
            ay = fmaf(ws, f.y, ay);
        }
        float2 bb = ((const float2*)b2)[lane];
        float zx = di * ax + bb.x;
        float zy = di * ay + bb.y;
        float m = fmaxf(zx, zy);
#pragma unroll
        for (int o = 16; o; o >>= 1) m = fmaxf(m, __shfl_xor_sync(0xffffffffu, m, o));
        float s = expf(zx - m) + expf(zy - m);
#pragma unroll
        for (int o = 16; o; o >>= 1) s += __shfl_xor_sync(0xffffffffu, s, o);
        float lse = m + logf(s);
        float2 r; r.x = zx - lse; r.y = zy - lse;
        ((float2*)(out + (size_t)w * DOUT))[lane] = r;
    }
}

// ---------------- launch ------------------------------------------------------
extern "C" void kernel_launch(void* const* d_in, const int* in_sizes, int n_in,
                              void* d_out, int out_size) {
    // Identify inputs by element count — all six counts are distinct.
    const float* x  = nullptr;
    const int*   ei = nullptr;
    const float* W1 = nullptr;
    const float* b1 = nullptr;
    const float* W2 = nullptr;
    const float* b2 = nullptr;
    for (int i = 0; i < n_in; i++) {
        switch (in_sizes[i]) {
            case NN * DIN:    x  = (const float*)d_in[i]; break;  // 25600000
            case 2 * EE:      ei = (const int*)d_in[i];   break;  //  6400000
            case DIN * DHID:  W1 = (const float*)d_in[i]; break;  //    65536
            case DHID:        b1 = (const float*)d_in[i]; break;  //      256
            case DHID * DOUT: W2 = (const float*)d_in[i]; break;  //    16384
            case DOUT:        b2 = (const float*)d_in[i]; break;  //       64
            default: break;
        }
    }
    float* out = (float*)d_out;
    const int* src = ei;        // row-major (2, E): row 0 = src, row 1 = dst
    const int* dst = ei + EE;

    // Only g_deg needs zeroing (h1/a1/h2 are fully overwritten before read).
    int* p_deg;  cudaGetSymbolAddress((void**)&p_deg, g_deg);
    cudaMemsetAsync(p_deg, 0, NN * sizeof(int));

    // CSR build + normalization
    k_count<<<2048, 256>>>(dst, EE);
    k_scan<<<1, 1024>>>();
    k_fill<<<2048, 256>>>(src, dst, EE);
    k_dinv<<<512, 256>>>();

    // layer 1
    k_gemm1<<<2 * ((NN + 127) / 128), 256>>>(x, W1);
    k_agg1<<<12500, 256>>>(b1);

    // layer 2
    k_gemm2<<<(NN + 127) / 128, 256>>>(W2);
    k_agg2<<<12500, 256>>>(b2, out);
}

// round 9
// speedup vs baseline: 1.2439x; 1.0616x over previous
#include <cuda_runtime.h>
#include <cuda_bf16.h>
#include <math.h>

#define NN   100000
#define EE   3200000
#define DIN  256
#define DHID 256
#define DOUT 64

// ---------------- scratch (__device__ globals; no allocation allowed) -------
__device__ int   g_deg[NN];
__device__ int   g_off[NN + 1];
__device__ int   g_cur[NN];
__device__ float g_dinv[NN];
__device__ int   g_csr[EE];
__device__ __align__(16) __nv_bfloat16 g_h1[(size_t)NN * DHID];  // bf16 x@W1
__device__ __align__(16) __nv_bfloat16 g_a1[(size_t)NN * DHID];  // bf16 relu(agg)
__device__ __align__(16) __nv_bfloat16 g_h2[(size_t)NN * DOUT];  // bf16 a1@W2

// ---------------- f32x2 packed-FMA helpers (sm_10x) --------------------------
__device__ __forceinline__ unsigned long long packf2(float x, float y) {
    unsigned long long r;
    asm("mov.b64 %0, {%1, %2};" : "=l"(r) : "f"(x), "f"(y));
    return r;
}
__device__ __forceinline__ void fmaf2(unsigned long long& d,
                                      unsigned long long a,
                                      unsigned long long b) {
    asm("fma.rn.f32x2 %0, %1, %2, %0;" : "+l"(d) : "l"(a), "l"(b));
}
__device__ __forceinline__ void unpackf2(unsigned long long v, float& x, float& y) {
    asm("mov.b64 {%0, %1}, %2;" : "=f"(x), "=f"(y) : "l"(v));
}
// bf16x2 from (lo, hi) floats
__device__ __forceinline__ unsigned int bf2(float lo, float hi) {
    unsigned int r;
    asm("cvt.rn.bf16x2.f32 %0, %1, %2;" : "=r"(r) : "f"(hi), "f"(lo));
    return r;
}
__device__ __forceinline__ float2 ubf2f(unsigned int u) {
    return __bfloat1622float2(*reinterpret_cast<const __nv_bfloat162*>(&u));
}

// ---------------- degree / CSR build (grid-stride everywhere) ---------------
extern "C" __global__ __launch_bounds__(256) void k_count(const int* dst, int e) {
    for (int i = blockIdx.x * blockDim.x + threadIdx.x; i < e;
         i += gridDim.x * blockDim.x)
        atomicAdd(&g_deg[dst[i]], 1);
}

extern "C" __global__ __launch_bounds__(1024) void k_scan() {
    __shared__ int partial[1024];
    int t = threadIdx.x;
    const int CH = (NN + 1023) / 1024;
    int start = t * CH;
    int end   = start + CH; if (end > NN) end = NN;
    int s = 0;
    for (int i = start; i < end; i++) s += g_deg[i];
    partial[t] = s;
    __syncthreads();
    for (int d = 1; d < 1024; d <<= 1) {
        int v = (t >= d) ? partial[t - d] : 0;
        __syncthreads();
        partial[t] += v;
        __syncthreads();
    }
    int run = (t > 0) ? partial[t - 1] : 0;
    for (int i = start; i < end; i++) {
        g_off[i] = run;
        g_cur[i] = run;
        run += g_deg[i];
    }
    if (t == 1023) g_off[NN] = partial[1023];
}

extern "C" __global__ __launch_bounds__(256) void k_fill(const int* src,
                                                         const int* dst, int e) {
    for (int i = blockIdx.x * blockDim.x + threadIdx.x; i < e;
         i += gridDim.x * blockDim.x) {
        int p = atomicAdd(&g_cur[dst[i]], 1);
        g_csr[p] = src[i];
    }
}

extern "C" __global__ __launch_bounds__(256) void k_dinv() {
    for (int i = blockIdx.x * blockDim.x + threadIdx.x; i < NN;
         i += gridDim.x * blockDim.x)
        g_dinv[i] = rsqrtf((float)(g_deg[i] + 1));   // +1 self-loop
}

// ---------------- GEMM 1: g_h1(bf16) = x @ W1 (M=NN, N=256, K=256) -----------
extern "C" __global__ __launch_bounds__(256) void k_gemm1(
    const float* __restrict__ A, const float* __restrict__ B) {
    __shared__ __align__(16) float As[8][128];
    __shared__ __align__(16) float Bs[8][128];
    const int tid = threadIdx.x;
    const int bx  = blockIdx.x & 1;
    const int by  = blockIdx.x >> 1;
    const int m0  = by * 128;
    const int n0  = bx * 128;
    const int tx  = tid & 15;
    const int ty  = tid >> 4;
    const int a_row = tid >> 1;
    const int a_kq  = (tid & 1) * 4;
    const int b_row = tid >> 5;
    const int b_col = (tid & 31) * 4;

    unsigned long long acc[8][4];
#pragma unroll
    for (int i = 0; i < 8; i++)
#pragma unroll
        for (int j = 0; j < 4; j++) acc[i][j] = 0ull;

    for (int k0 = 0; k0 < DIN; k0 += 8) {
        int gm = m0 + a_row;
        float4 va = make_float4(0.f, 0.f, 0.f, 0.f);
        if (gm < NN) va = *(const float4*)(A + (size_t)gm * DIN + k0 + a_kq);
        As[a_kq + 0][a_row] = va.x;
        As[a_kq + 1][a_row] = va.y;
        As[a_kq + 2][a_row] = va.z;
        As[a_kq + 3][a_row] = va.w;
        float4 vb = *(const float4*)(B + (size_t)(k0 + b_row) * DHID + n0 + b_col);
        *(float4*)&Bs[b_row][b_col] = vb;
        __syncthreads();
#pragma unroll
        for (int kk = 0; kk < 8; kk++) {
            unsigned long long ad[8];
#pragma unroll
            for (int i = 0; i < 8; i++) {
                float av = As[kk][ty * 8 + i];
                ad[i] = packf2(av, av);
            }
            const unsigned long long* bp =
                (const unsigned long long*)&Bs[kk][tx * 8];
            unsigned long long bv[4];
#pragma unroll
            for (int j = 0; j < 4; j++) bv[j] = bp[j];
#pragma unroll
            for (int i = 0; i < 8; i++)
#pragma unroll
                for (int j = 0; j < 4; j++) fmaf2(acc[i][j], ad[i], bv[j]);
        }
        __syncthreads();
    }
#pragma unroll
    for (int i = 0; i < 8; i++) {
        int row = m0 + ty * 8 + i;
        if (row < NN) {
            uint4 pk;
            float lo, hi;
            unpackf2(acc[i][0], lo, hi); pk.x = bf2(lo, hi);
            unpackf2(acc[i][1], lo, hi); pk.y = bf2(lo, hi);
            unpackf2(acc[i][2], lo, hi); pk.z = bf2(lo, hi);
            unpackf2(acc[i][3], lo, hi); pk.w = bf2(lo, hi);
            *(uint4*)(g_h1 + (size_t)row * DHID + n0 + tx * 8) = pk;
        }
    }
}

// ---------------- GEMM 2: g_h2(bf16) = g_a1(bf16) @ W2 (M=NN, N=64, K=256) ---
extern "C" __global__ __launch_bounds__(256) void k_gemm2(
    const float* __restrict__ B) {
    __shared__ __align__(16) float As[8][128];
    __shared__ __align__(16) float Bs[8][64];
    const int tid = threadIdx.x;
    const int m0  = blockIdx.x * 128;
    const int tx  = tid & 15;
    const int ty  = tid >> 4;
    const int b_row = tid >> 4;
    const int b_col = (tid & 15) * 4;

    unsigned long long acc[8][2];
#pragma unroll
    for (int i = 0; i < 8; i++) { acc[i][0] = 0ull; acc[i][1] = 0ull; }

    for (int k0 = 0; k0 < DHID; k0 += 8) {
        // A tile: 128 rows x 8 k's of bf16 -> 128 threads each load one uint4 (8 bf16)
        if (tid < 128) {
            int gm = m0 + tid;
            uint4 va = make_uint4(0u, 0u, 0u, 0u);
            if (gm < NN) va = *(const uint4*)(g_a1 + (size_t)gm * DHID + k0);
            float2 f0 = ubf2f(va.x), f1 = ubf2f(va.y),
                   f2 = ubf2f(va.z), f3 = ubf2f(va.w);
            As[0][tid] = f0.x; As[1][tid] = f0.y;
            As[2][tid] = f1.x; As[3][tid] = f1.y;
            As[4][tid] = f2.x; As[5][tid] = f2.y;
            As[6][tid] = f3.x; As[7][tid] = f3.y;
        }
        if (b_row < 8) {
            float4 vb = *(const float4*)(B + (size_t)(k0 + b_row) * DOUT + b_col);
            *(float4*)&Bs[b_row][b_col] = vb;
        }
        __syncthreads();
#pragma unroll
        for (int kk = 0; kk < 8; kk++) {
            const unsigned long long* bp =
                (const unsigned long long*)&Bs[kk][tx * 4];
            unsigned long long bv0 = bp[0], bv1 = bp[1];
#pragma unroll
            for (int i = 0; i < 8; i++) {
                float av = As[kk][ty * 8 + i];
                unsigned long long ad = packf2(av, av);
                fmaf2(acc[i][0], ad, bv0);
                fmaf2(acc[i][1], ad, bv1);
            }
        }
        __syncthreads();
    }
#pragma unroll
    for (int i = 0; i < 8; i++) {
        int row = m0 + ty * 8 + i;
        if (row < NN) {
            uint2 pk;
            float lo, hi;
            unpackf2(acc[i][0], lo, hi); pk.x = bf2(lo, hi);
            unpackf2(acc[i][1], lo, hi); pk.y = bf2(lo, hi);
            *(uint2*)(g_h2 + (size_t)row * DOUT + tx * 4) = pk;
        }
    }
}

// ---------------- layer-1 aggregation: one warp per dst, unroll-4 ------------
__device__ __forceinline__ void acc_row1(float acc[8], float ws, uint4 v) {
    const unsigned int* u = (const unsigned int*)&v;
#pragma unroll
    for (int q = 0; q < 4; q++) {
        float2 f = ubf2f(u[q]);
        acc[2 * q]     = fmaf(ws, f.x, acc[2 * q]);
        acc[2 * q + 1] = fmaf(ws, f.y, acc[2 * q + 1]);
    }
}

extern "C" __global__ __launch_bounds__(256) void k_agg1(const float* __restrict__ b1) {
    int lane = threadIdx.x & 31;
    int warps = (gridDim.x * blockDim.x) >> 5;
    for (int w = (blockIdx.x * blockDim.x + threadIdx.x) >> 5; w < NN; w += warps) {
        float di = g_dinv[w];
        float acc[8];
        {
            uint4 v = __ldg(&((const uint4*)(g_h1 + (size_t)w * DHID))[lane]);
            const unsigned int* u = (const unsigned int*)&v;
#pragma unroll
            for (int q = 0; q < 4; q++) {
                float2 f = ubf2f(u[q]);
                acc[2 * q]     = di * f.x;
                acc[2 * q + 1] = di * f.y;
            }
        }
        int e   = g_off[w];
        int end = g_off[w + 1];
        for (; e + 4 <= end; e += 4) {
            int s0 = __ldg(&g_csr[e]);
            int s1 = __ldg(&g_csr[e + 1]);
            int s2 = __ldg(&g_csr[e + 2]);
            int s3 = __ldg(&g_csr[e + 3]);
            float w0 = __ldg(&g_dinv[s0]);
            float w1 = __ldg(&g_dinv[s1]);
            float w2 = __ldg(&g_dinv[s2]);
            float w3 = __ldg(&g_dinv[s3]);
            uint4 v0 = __ldg(&((const uint4*)(g_h1 + (size_t)s0 * DHID))[lane]);
            uint4 v1 = __ldg(&((const uint4*)(g_h1 + (size_t)s1 * DHID))[lane]);
            uint4 v2 = __ldg(&((const uint4*)(g_h1 + (size_t)s2 * DHID))[lane]);
            uint4 v3 = __ldg(&((const uint4*)(g_h1 + (size_t)s3 * DHID))[lane]);
            acc_row1(acc, w0, v0);
            acc_row1(acc, w1, v1);
            acc_row1(acc, w2, v2);
            acc_row1(acc, w3, v3);
        }
        for (; e < end; e++) {
            int   s  = __ldg(&g_csr[e]);
            float ws = __ldg(&g_dinv[s]);
            uint4 v  = __ldg(&((const uint4*)(g_h1 + (size_t)s * DHID))[lane]);
            acc_row1(acc, ws, v);
        }
        float4 bb0 = ((const float4*)b1)[lane * 2];
        float4 bb1 = ((const float4*)b1)[lane * 2 + 1];
        uint4 pk;
        pk.x = bf2(fmaxf(di * acc[0] + bb0.x, 0.f), fmaxf(di * acc[1] + bb0.y, 0.f));
        pk.y = bf2(fmaxf(di * acc[2] + bb0.z, 0.f), fmaxf(di * acc[3] + bb0.w, 0.f));
        pk.z = bf2(fmaxf(di * acc[4] + bb1.x, 0.f), fmaxf(di * acc[5] + bb1.y, 0.f));
        pk.w = bf2(fmaxf(di * acc[6] + bb1.z, 0.f), fmaxf(di * acc[7] + bb1.w, 0.f));
        ((uint4*)(g_a1 + (size_t)w * DHID))[lane] = pk;
    }
}

// ---------------- layer-2 aggregation + bias + log_softmax, unroll-4 ---------
extern "C" __global__ __launch_bounds__(256) void k_agg2(const float* __restrict__ b2,
                                                         float* __restrict__ out) {
    int lane = threadIdx.x & 31;
    int warps = (gridDim.x * blockDim.x) >> 5;
    for (int w = (blockIdx.x * blockDim.x + threadIdx.x) >> 5; w < NN; w += warps) {
        float di = g_dinv[w];
        float ax, ay;
        {
            unsigned int v = __ldg(&((const unsigned int*)(g_h2 + (size_t)w * DOUT))[lane]);
            float2 f = ubf2f(v);
            ax = di * f.x;
            ay = di * f.y;
        }
        int e   = g_off[w];
        int end = g_off[w + 1];
        for (; e + 4 <= end; e += 4) {
            int s0 = __ldg(&g_csr[e]);
            int s1 = __ldg(&g_csr[e + 1]);
            int s2 = __ldg(&g_csr[e + 2]);
            int s3 = __ldg(&g_csr[e + 3]);
            float w0 = __ldg(&g_dinv[s0]);
            float w1 = __ldg(&g_dinv[s1]);
            float w2 = __ldg(&g_dinv[s2]);
            float w3 = __ldg(&g_dinv[s3]);
            unsigned int v0 = __ldg(&((const unsigned int*)(g_h2 + (size_t)s0 * DOUT))[lane]);
            unsigned int v1 = __ldg(&((const unsigned int*)(g_h2 + (size_t)s1 * DOUT))[lane]);
            unsigned int v2 = __ldg(&((const unsigned int*)(g_h2 + (size_t)s2 * DOUT))[lane]);
            unsigned int v3 = __ldg(&((const unsigned int*)(g_h2 + (size_t)s3 * DOUT))[lane]);
            float2 f0 = ubf2f(v0), f1 = ubf2f(v1), f2 = ubf2f(v2), f3 = ubf2f(v3);
            ax = fmaf(w0, f0.x, ax); ay = fmaf(w0, f0.y, ay);
            ax = fmaf(w1, f1.x, ax); ay = fmaf(w1, f1.y, ay);
            ax = fmaf(w2, f2.x, ax); ay = fmaf(w2, f2.y, ay);
            ax = fmaf(w3, f3.x, ax); ay = fmaf(w3, f3.y, ay);
        }
        for (; e < end; e++) {
            int   s  = __ldg(&g_csr[e]);
            float ws = __ldg(&g_dinv[s]);
            unsigned int v = __ldg(&((const unsigned int*)(g_h2 + (size_t)s * DOUT))[lane]);
            float2 f = ubf2f(v);
            ax = fmaf(ws, f.x, ax);
            ay = fmaf(ws, f.y, ay);
        }
        float2 bb = ((const float2*)b2)[lane];
        float zx = di * ax + bb.x;
        float zy = di * ay + bb.y;
        float m = fmaxf(zx, zy);
#pragma unroll
        for (int o = 16; o; o >>= 1) m = fmaxf(m, __shfl_xor_sync(0xffffffffu, m, o));
        float s = expf(zx - m) + expf(zy - m);
#pragma unroll
        for (int o = 16; o; o >>= 1) s += __shfl_xor_sync(0xffffffffu, s, o);
        float lse = m + logf(s);
        float2 r; r.x = zx - lse; r.y = zy - lse;
        ((float2*)(out + (size_t)w * DOUT))[lane] = r;
    }
}

// ---------------- launch ------------------------------------------------------
extern "C" void kernel_launch(void* const* d_in, const int* in_sizes, int n_in,
                              void* d_out, int out_size) {
    // Identify inputs by element count — all six counts are distinct.
    const float* x  = nullptr;
    const int*   ei = nullptr;
    const float* W1 = nullptr;
    const float* b1 = nullptr;
    const float* W2 = nullptr;
    const float* b2 = nullptr;
    for (int i = 0; i < n_in; i++) {
        switch (in_sizes[i]) {
            case NN * DIN:    x  = (const float*)d_in[i]; break;  // 25600000
            case 2 * EE:      ei = (const int*)d_in[i];   break;  //  6400000
            case DIN * DHID:  W1 = (const float*)d_in[i]; break;  //    65536
            case DHID:        b1 = (const float*)d_in[i]; break;  //      256
            case DHID * DOUT: W2 = (const float*)d_in[i]; break;  //    16384
            case DOUT:        b2 = (const float*)d_in[i]; break;  //       64
            default: break;
        }
    }
    float* out = (float*)d_out;
    const int* src = ei;        // row-major (2, E): row 0 = src, row 1 = dst
    const int* dst = ei + EE;

    // Only g_deg needs zeroing (h1/a1/h2 are fully overwritten before read).
    int* p_deg;  cudaGetSymbolAddress((void**)&p_deg, g_deg);
    cudaMemsetAsync(p_deg, 0, NN * sizeof(int));

    // CSR build + normalization
    k_count<<<2048, 256>>>(dst, EE);
    k_scan<<<1, 1024>>>();
    k_fill<<<2048, 256>>>(src, dst, EE);
    k_dinv<<<512, 256>>>();

    // layer 1
    k_gemm1<<<2 * ((NN + 127) / 128), 256>>>(x, W1);
    k_agg1<<<12500, 256>>>(b1);

    // layer 2
    k_gemm2<<<(NN + 127) / 128, 256>>>(W2);
    k_agg2<<<12500, 256>>>(b2, out);
}

// round 10
// speedup vs baseline: 1.7848x; 1.4348x over previous
#include <cuda_runtime.h>
#include <cuda_bf16.h>
#include <math.h>

#define NN   100000
#define EE   3200000
#define DIN  256
#define DHID 256
#define DOUT 64

// ---------------- scratch (__device__ globals; no allocation allowed) -------
__device__ int   g_deg[NN];
__device__ int   g_off[NN + 1];
__device__ int   g_cur[NN];
__device__ float g_dinv[NN];
__device__ int   g_csr[EE];
__device__ __align__(16) __nv_bfloat16 g_h1[(size_t)NN * DHID];  // bf16 x@W1
__device__ __align__(16) __nv_bfloat16 g_a1[(size_t)NN * DHID];  // bf16 relu(agg)
__device__ __align__(16) __nv_bfloat16 g_h2[(size_t)NN * DOUT];  // bf16 a1@W2

// ---------------- helpers ----------------------------------------------------
__device__ __forceinline__ unsigned int bf2(float lo, float hi) {
    unsigned int r;
    asm("cvt.rn.bf16x2.f32 %0, %1, %2;" : "=r"(r) : "f"(hi), "f"(lo));
    return r;
}
__device__ __forceinline__ float2 ubf2f(unsigned int u) {
    return __bfloat1622float2(*reinterpret_cast<const __nv_bfloat162*>(&u));
}
__device__ __forceinline__ unsigned int smem_u32(const void* p) {
    return (unsigned int)__cvta_generic_to_shared(p);
}
__device__ __forceinline__ void ldsm_x4(unsigned int addr, unsigned int& r0,
                                        unsigned int& r1, unsigned int& r2,
                                        unsigned int& r3) {
    asm volatile("ldmatrix.sync.aligned.m8n8.x4.shared.b16 {%0,%1,%2,%3}, [%4];"
                 : "=r"(r0), "=r"(r1), "=r"(r2), "=r"(r3) : "r"(addr));
}
__device__ __forceinline__ void ldsm_x4t(unsigned int addr, unsigned int& r0,
                                         unsigned int& r1, unsigned int& r2,
                                         unsigned int& r3) {
    asm volatile("ldmatrix.sync.aligned.m8n8.x4.trans.shared.b16 {%0,%1,%2,%3}, [%4];"
                 : "=r"(r0), "=r"(r1), "=r"(r2), "=r"(r3) : "r"(addr));
}
__device__ __forceinline__ void mma_bf16(float c[4],
                                         unsigned int a0, unsigned int a1,
                                         unsigned int a2, unsigned int a3,
                                         unsigned int b0, unsigned int b1) {
    asm volatile(
        "mma.sync.aligned.m16n8k16.row.col.f32.bf16.bf16.f32 "
        "{%0,%1,%2,%3},{%4,%5,%6,%7},{%8,%9},{%0,%1,%2,%3};"
        : "+f"(c[0]), "+f"(c[1]), "+f"(c[2]), "+f"(c[3])
        : "r"(a0), "r"(a1), "r"(a2), "r"(a3), "r"(b0), "r"(b1));
}

// ---------------- degree / CSR build (grid-stride everywhere) ---------------
extern "C" __global__ __launch_bounds__(256) void k_count(const int* dst, int e) {
    for (int i = blockIdx.x * blockDim.x + threadIdx.x; i < e;
         i += gridDim.x * blockDim.x)
        atomicAdd(&g_deg[dst[i]], 1);
}

extern "C" __global__ __launch_bounds__(1024) void k_scan() {
    __shared__ int partial[1024];
    int t = threadIdx.x;
    const int CH = (NN + 1023) / 1024;
    int start = t * CH;
    int end   = start + CH; if (end > NN) end = NN;
    int s = 0;
    for (int i = start; i < end; i++) s += g_deg[i];
    partial[t] = s;
    __syncthreads();
    for (int d = 1; d < 1024; d <<= 1) {
        int v = (t >= d) ? partial[t - d] : 0;
        __syncthreads();
        partial[t] += v;
        __syncthreads();
    }
    int run = (t > 0) ? partial[t - 1] : 0;
    for (int i = start; i < end; i++) {
        g_off[i] = run;
        g_cur[i] = run;
        run += g_deg[i];
    }
    if (t == 1023) g_off[NN] = partial[1023];
}

extern "C" __global__ __launch_bounds__(256) void k_fill(const int* src,
                                                         const int* dst, int e) {
    for (int i = blockIdx.x * blockDim.x + threadIdx.x; i < e;
         i += gridDim.x * blockDim.x) {
        int p = atomicAdd(&g_cur[dst[i]], 1);
        g_csr[p] = src[i];
    }
}

extern "C" __global__ __launch_bounds__(256) void k_dinv() {
    for (int i = blockIdx.x * blockDim.x + threadIdx.x; i < NN;
         i += gridDim.x * blockDim.x)
        g_dinv[i] = rsqrtf((float)(g_deg[i] + 1));   // +1 self-loop
}

// ---------------- GEMM 1 (tensor core): g_h1(bf16) = x @ W1 ------------------
// BM=128, BN=256 (full N -> x read once), BK=16, 256 thr, 8 warps 2Mx4N,
// warp tile 64x64 = 4 m16 x 8 n8 mma.m16n8k16.
#define AP1 24    // A smem row pitch (bf16): 16 data + 8 pad -> LDSM conflict-free
#define BP1 264   // B smem row pitch (bf16): 256 data + 8 pad
extern "C" __global__ __launch_bounds__(256) void k_gemm1(
    const float* __restrict__ A, const float* __restrict__ B) {
    __shared__ __align__(16) __nv_bfloat16 Asm[128 * AP1];
    __shared__ __align__(16) __nv_bfloat16 Bsm[16 * BP1];
    const int tid  = threadIdx.x;
    const int wid  = tid >> 5;
    const int lane = tid & 31;
    const int m0   = blockIdx.x * 128;
    const int wm   = (wid & 1) * 64;
    const int wn   = (wid >> 1) * 64;

    float c[4][8][4];
#pragma unroll
    for (int i = 0; i < 4; i++)
#pragma unroll
        for (int j = 0; j < 8; j++)
#pragma unroll
            for (int q = 0; q < 4; q++) c[i][j][q] = 0.f;

    for (int k0 = 0; k0 < DIN; k0 += 16) {
        // stage A (x fp32 -> bf16): 128x16 = 512 float4, 2 per thread
#pragma unroll
        for (int i = 0; i < 2; i++) {
            int idx = tid + i * 256;
            int row = idx >> 2;
            int kq  = (idx & 3) * 4;
            int gm  = m0 + row;
            float4 v = make_float4(0.f, 0.f, 0.f, 0.f);
            if (gm < NN) v = *(const float4*)(A + (size_t)gm * DIN + k0 + kq);
            *(uint2*)&Asm[row * AP1 + kq] = make_uint2(bf2(v.x, v.y), bf2(v.z, v.w));
        }
        // stage B (W1 fp32 -> bf16): 16x256 = 1024 float4, 4 per thread
#pragma unroll
        for (int i = 0; i < 4; i++) {
            int idx = tid + i * 256;
            int kr  = idx >> 6;
            int nc  = (idx & 63) * 4;
            float4 v = *(const float4*)(B + (size_t)(k0 + kr) * DHID + nc);
            *(uint2*)&Bsm[kr * BP1 + nc] = make_uint2(bf2(v.x, v.y), bf2(v.z, v.w));
        }
        __syncthreads();

        unsigned int a[4][4];
#pragma unroll
        for (int ms = 0; ms < 4; ms++) {
            int row = wm + ms * 16 + (lane & 15);
            int col = (lane >> 4) * 8;
            ldsm_x4(smem_u32(&Asm[row * AP1 + col]),
                    a[ms][0], a[ms][1], a[ms][2], a[ms][3]);
        }
        unsigned int b[8][2];
#pragma unroll
        for (int nt = 0; nt < 4; nt++) {
            int k  = lane & 15;                     // 0-7 / 8-15 per lane group
            int nb = wn + nt * 16 + (lane >> 4) * 8;
            ldsm_x4t(smem_u32(&Bsm[k * BP1 + nb]),
                     b[2 * nt][0], b[2 * nt][1], b[2 * nt + 1][0], b[2 * nt + 1][1]);
        }
#pragma unroll
        for (int ms = 0; ms < 4; ms++)
#pragma unroll
            for (int ns = 0; ns < 8; ns++)
                mma_bf16(c[ms][ns], a[ms][0], a[ms][1], a[ms][2], a[ms][3],
                         b[ns][0], b[ns][1]);
        __syncthreads();
    }
    // epilogue: write bf16
#pragma unroll
    for (int ms = 0; ms < 4; ms++) {
        int r0 = m0 + wm + ms * 16 + (lane >> 2);
        int r1 = r0 + 8;
#pragma unroll
        for (int ns = 0; ns < 8; ns++) {
            int col = wn + ns * 8 + (lane & 3) * 2;
            if (r0 < NN)
                *(unsigned int*)(g_h1 + (size_t)r0 * DHID + col) =
                    bf2(c[ms][ns][0], c[ms][ns][1]);
            if (r1 < NN)
                *(unsigned int*)(g_h1 + (size_t)r1 * DHID + col) =
                    bf2(c[ms][ns][2], c[ms][ns][3]);
        }
    }
}

// ---------------- GEMM 2 (tensor core): g_h2(bf16) = g_a1(bf16) @ W2 ---------
// BM=128, BN=64, BK=16, 128 thr, 4 warps 2Mx2N, warp tile 64x32.
#define BP2 72    // W2 smem row pitch (bf16): 64 + 8 pad
extern "C" __global__ __launch_bounds__(128) void k_gemm2(
    const float* __restrict__ B) {
    __shared__ __align__(16) __nv_bfloat16 Asm[128 * AP1];
    __shared__ __align__(16) __nv_bfloat16 Bsm[16 * BP2];
    const int tid  = threadIdx.x;
    const int wid  = tid >> 5;
    const int lane = tid & 31;
    const int m0   = blockIdx.x * 128;
    const int wm   = (wid & 1) * 64;
    const int wn   = (wid >> 1) * 32;

    float c[4][4][4];
#pragma unroll
    for (int i = 0; i < 4; i++)
#pragma unroll
        for (int j = 0; j < 4; j++)
#pragma unroll
            for (int q = 0; q < 4; q++) c[i][j][q] = 0.f;

    for (int k0 = 0; k0 < DHID; k0 += 16) {
        // stage A (already bf16): 128 rows x 16 bf16 = 256 uint4, 2 per thread
#pragma unroll
        for (int i = 0; i < 2; i++) {
            int idx  = tid + i * 128;
            int row  = idx >> 1;
            int half = (idx & 1) * 8;
            int gm   = m0 + row;
            uint4 v = make_uint4(0u, 0u, 0u, 0u);
            if (gm < NN) v = *(const uint4*)(g_a1 + (size_t)gm * DHID + k0 + half);
            *(uint4*)&Asm[row * AP1 + half] = v;
        }
        // stage B (W2 fp32 -> bf16): 16x64 = 256 float4, 2 per thread
#pragma unroll
        for (int i = 0; i < 2; i++) {
            int idx = tid + i * 128;
            int kr  = idx >> 4;
            int nc  = (idx & 15) * 4;
            float4 v = *(const float4*)(B + (size_t)(k0 + kr) * DOUT + nc);
            *(uint2*)&Bsm[kr * BP2 + nc] = make_uint2(bf2(v.x, v.y), bf2(v.z, v.w));
        }
        __syncthreads();

        unsigned int a[4][4];
#pragma unroll
        for (int ms = 0; ms < 4; ms++) {
            int row = wm + ms * 16 + (lane & 15);
            int col = (lane >> 4) * 8;
            ldsm_x4(smem_u32(&Asm[row * AP1 + col]),
                    a[ms][0], a[ms][1], a[ms][2], a[ms][3]);
        }
        unsigned int b[4][2];
#pragma unroll
        for (int nt = 0; nt < 2; nt++) {
            int k  = lane & 15;
            int nb = wn + nt * 16 + (lane >> 4) * 8;
            ldsm_x4t(smem_u32(&Bsm[k * BP2 + nb]),
                     b[2 * nt][0], b[2 * nt][1], b[2 * nt + 1][0], b[2 * nt + 1][1]);
        }
#pragma unroll
        for (int ms = 0; ms < 4; ms++)
#pragma unroll
            for (int ns = 0; ns < 4; ns++)
                mma_bf16(c[ms][ns], a[ms][0], a[ms][1], a[ms][2], a[ms][3],
                         b[ns][0], b[ns][1]);
        __syncthreads();
    }
#pragma unroll
    for (int ms = 0; ms < 4; ms++) {
        int r0 = m0 + wm + ms * 16 + (lane >> 2);
        int r1 = r0 + 8;
#pragma unroll
        for (int ns = 0; ns < 4; ns++) {
            int col = wn + ns * 8 + (lane & 3) * 2;
            if (r0 < NN)
                *(unsigned int*)(g_h2 + (size_t)r0 * DOUT + col) =
                    bf2(c[ms][ns][0], c[ms][ns][1]);
            if (r1 < NN)
                *(unsigned int*)(g_h2 + (size_t)r1 * DOUT + col) =
                    bf2(c[ms][ns][2], c[ms][ns][3]);
        }
    }
}

// ---------------- layer-1 aggregation: one warp per dst, unroll-4 ------------
__device__ __forceinline__ void acc_row1(float acc[8], float ws, uint4 v) {
    const unsigned int* u = (const unsigned int*)&v;
#pragma unroll
    for (int q = 0; q < 4; q++) {
        float2 f = ubf2f(u[q]);
        acc[2 * q]     = fmaf(ws, f.x, acc[2 * q]);
        acc[2 * q + 1] = fmaf(ws, f.y, acc[2 * q + 1]);
    }
}

extern "C" __global__ __launch_bounds__(256) void k_agg1(const float* __restrict__ b1) {
    int lane = threadIdx.x & 31;
    int warps = (gridDim.x * blockDim.x) >> 5;
    for (int w = (blockIdx.x * blockDim.x + threadIdx.x) >> 5; w < NN; w += warps) {
        float di = g_dinv[w];
        float acc[8];
        {
            uint4 v = __ldg(&((const uint4*)(g_h1 + (size_t)w * DHID))[lane]);
            const unsigned int* u = (const unsigned int*)&v;
#pragma unroll
            for (int q = 0; q < 4; q++) {
                float2 f = ubf2f(u[q]);
                acc[2 * q]     = di * f.x;
                acc[2 * q + 1] = di * f.y;
            }
        }
        int e   = g_off[w];
        int end = g_off[w + 1];
        for (; e + 4 <= end; e += 4) {
            int s0 = __ldg(&g_csr[e]);
            int s1 = __ldg(&g_csr[e + 1]);
            int s2 = __ldg(&g_csr[e + 2]);
            int s3 = __ldg(&g_csr[e + 3]);
            float w0 = __ldg(&g_dinv[s0]);
            float w1 = __ldg(&g_dinv[s1]);
            float w2 = __ldg(&g_dinv[s2]);
            float w3 = __ldg(&g_dinv[s3]);
            uint4 v0 = __ldg(&((const uint4*)(g_h1 + (size_t)s0 * DHID))[lane]);
            uint4 v1 = __ldg(&((const uint4*)(g_h1 + (size_t)s1 * DHID))[lane]);
            uint4 v2 = __ldg(&((const uint4*)(g_h1 + (size_t)s2 * DHID))[lane]);
            uint4 v3 = __ldg(&((const uint4*)(g_h1 + (size_t)s3 * DHID))[lane]);
            acc_row1(acc, w0, v0);
            acc_row1(acc, w1, v1);
            acc_row1(acc, w2, v2);
            acc_row1(acc, w3, v3);
        }
        for (; e < end; e++) {
            int   s  = __ldg(&g_csr[e]);
            float ws = __ldg(&g_dinv[s]);
            uint4 v  = __ldg(&((const uint4*)(g_h1 + (size_t)s * DHID))[lane]);
            acc_row1(acc, ws, v);
        }
        float4 bb0 = ((const float4*)b1)[lane * 2];
        float4 bb1 = ((const float4*)b1)[lane * 2 + 1];
        uint4 pk;
        pk.x = bf2(fmaxf(di * acc[0] + bb0.x, 0.f), fmaxf(di * acc[1] + bb0.y, 0.f));
        pk.y = bf2(fmaxf(di * acc[2] + bb0.z, 0.f), fmaxf(di * acc[3] + bb0.w, 0.f));
        pk.z = bf2(fmaxf(di * acc[4] + bb1.x, 0.f), fmaxf(di * acc[5] + bb1.y, 0.f));
        pk.w = bf2(fmaxf(di * acc[6] + bb1.z, 0.f), fmaxf(di * acc[7] + bb1.w, 0.f));
        ((uint4*)(g_a1 + (size_t)w * DHID))[lane] = pk;
    }
}

// ---------------- layer-2 aggregation + bias + log_softmax, unroll-4 ---------
extern "C" __global__ __launch_bounds__(256) void k_agg2(const float* __restrict__ b2,
                                                         float* __restrict__ out) {
    int lane = threadIdx.x & 31;
    int warps = (gridDim.x * blockDim.x) >> 5;
    for (int w = (blockIdx.x * blockDim.x + threadIdx.x) >> 5; w < NN; w += warps) {
        float di = g_dinv[w];
        float ax, ay;
        {
            unsigned int v = __ldg(&((const unsigned int*)(g_h2 + (size_t)w * DOUT))[lane]);
            float2 f = ubf2f(v);
            ax = di * f.x;
            ay = di * f.y;
        }
        int e   = g_off[w];
        int end = g_off[w + 1];
        for (; e + 4 <= end; e += 4) {
            int s0 = __ldg(&g_csr[e]);
            int s1 = __ldg(&g_csr[e + 1]);
            int s2 = __ldg(&g_csr[e + 2]);
            int s3 = __ldg(&g_csr[e + 3]);
            float w0 = __ldg(&g_dinv[s0]);
            float w1 = __ldg(&g_dinv[s1]);
            float w2 = __ldg(&g_dinv[s2]);
            float w3 = __ldg(&g_dinv[s3]);
            unsigned int v0 = __ldg(&((const unsigned int*)(g_h2 + (size_t)s0 * DOUT))[lane]);
            unsigned int v1 = __ldg(&((const unsigned int*)(g_h2 + (size_t)s1 * DOUT))[lane]);
            unsigned int v2 = __ldg(&((const unsigned int*)(g_h2 + (size_t)s2 * DOUT))[lane]);
            unsigned int v3 = __ldg(&((const unsigned int*)(g_h2 + (size_t)s3 * DOUT))[lane]);
            float2 f0 = ubf2f(v0), f1 = ubf2f(v1), f2 = ubf2f(v2), f3 = ubf2f(v3);
            ax = fmaf(w0, f0.x, ax); ay = fmaf(w0, f0.y, ay);
            ax = fmaf(w1, f1.x, ax); ay = fmaf(w1, f1.y, ay);
            ax = fmaf(w2, f2.x, ax); ay = fmaf(w2, f2.y, ay);
            ax = fmaf(w3, f3.x, ax); ay = fmaf(w3, f3.y, ay);
        }
        for (; e < end; e++) {
            int   s  = __ldg(&g_csr[e]);
            float ws = __ldg(&g_dinv[s]);
            unsigned int v = __ldg(&((const unsigned int*)(g_h2 + (size_t)s * DOUT))[lane]);
            float2 f = ubf2f(v);
            ax = fmaf(ws, f.x, ax);
            ay = fmaf(ws, f.y, ay);
        }
        float2 bb = ((const float2*)b2)[lane];
        float zx = di * ax + bb.x;
        float zy = di * ay + bb.y;
        float m = fmaxf(zx, zy);
#pragma unroll
        for (int o = 16; o; o >>= 1) m = fmaxf(m, __shfl_xor_sync(0xffffffffu, m, o));
        float s = expf(zx - m) + expf(zy - m);
#pragma unroll
        for (int o = 16; o; o >>= 1) s += __shfl_xor_sync(0xffffffffu, s, o);
        float lse = m + logf(s);
        float2 r; r.x = zx - lse; r.y = zy - lse;
        ((float2*)(out + (size_t)w * DOUT))[lane] = r;
    }
}

// ---------------- launch ------------------------------------------------------
extern "C" void kernel_launch(void* const* d_in, const int* in_sizes, int n_in,
                              void* d_out, int out_size) {
    // Identify inputs by element count — all six counts are distinct.
    const float* x  = nullptr;
    const int*   ei = nullptr;
    const float* W1 = nullptr;
    const float* b1 = nullptr;
    const float* W2 = nullptr;
    const float* b2 = nullptr;
    for (int i = 0; i < n_in; i++) {
        switch (in_sizes[i]) {
            case NN * DIN:    x  = (const float*)d_in[i]; break;  // 25600000
            case 2 * EE:      ei = (const int*)d_in[i];   break;  //  6400000
            case DIN * DHID:  W1 = (const float*)d_in[i]; break;  //    65536
            case DHID:        b1 = (const float*)d_in[i]; break;  //      256
            case DHID * DOUT: W2 = (const float*)d_in[i]; break;  //    16384
            case DOUT:        b2 = (const float*)d_in[i]; break;  //       64
            default: break;
        }
    }
    float* out = (float*)d_out;
    const int* src = ei;        // row-major (2, E): row 0 = src, row 1 = dst
    const int* dst = ei + EE;

    // Only g_deg needs zeroing (h1/a1/h2 are fully overwritten before read).
    int* p_deg;  cudaGetSymbolAddress((void**)&p_deg, g_deg);
    cudaMemsetAsync(p_deg, 0, NN * sizeof(int));

    // CSR build + normalization
    k_count<<<2048, 256>>>(dst, EE);
    k_scan<<<1, 1024>>>();
    k_fill<<<2048, 256>>>(src, dst, EE);
    k_dinv<<<512, 256>>>();

    // layer 1
    k_gemm1<<<(NN + 127) / 128, 256>>>(x, W1);
    k_agg1<<<12500, 256>>>(b1);

    // layer 2
    k_gemm2<<<(NN + 127) / 128, 128>>>(W2);
    k_agg2<<<12500, 256>>>(b2, out);
}